// round 2
// baseline (speedup 1.0000x reference)
#include <cuda_runtime.h>
#include <math.h>

#define Bv 256
#define NT 197
#define CC 768
#define HH 12
#define DH 64
#define GRID 14
#define M_ROWS (Bv * NT)          // 50432 = 394*128
#define KT_STRIDE 224

// ---------------- scratch ----------------
__device__ float g_q[(size_t)Bv * HH * NT * DH];
__device__ float g_k[(size_t)Bv * HH * NT * DH];
__device__ float g_v[(size_t)Bv * HH * NT * DH];
__device__ float g_att[(size_t)Bv * NT * CC];

// ---------------- SGEMM: 128x128x8, 256 threads, 8x8 per thread ----------------
// MODE 0: C[m*N+n] = acc + bias[n]
// MODE 1: qkv scatter into g_q/g_k/g_v with layout (B,H,N,D)
template<int MODE>
__global__ __launch_bounds__(256, 2)
void sgemm_kernel(const float* __restrict__ A, const float* __restrict__ Bm,
                  const float* __restrict__ bias, float* __restrict__ C,
                  float* __restrict__ Cq, float* __restrict__ Ck, float* __restrict__ Cv,
                  int M, int N, int K)
{
    __shared__ float As[8][128];
    __shared__ float Bs[8][128];

    const int tid  = threadIdx.x;
    const int brow = blockIdx.y;
    const int bcol = blockIdx.x;
    const int tx = tid & 15;
    const int ty = tid >> 4;

    float acc[8][8];
    #pragma unroll
    for (int i = 0; i < 8; i++)
        #pragma unroll
        for (int j = 0; j < 8; j++) acc[i][j] = 0.f;

    const int a_r = tid >> 1;
    const int a_c = (tid & 1) * 4;
    const int b_k = tid >> 5;
    const int b_c = (tid & 31) * 4;

    const float* Ap = A + (size_t)(brow * 128 + a_r) * K + a_c;
    const float* Bp = Bm + (size_t)b_k * N + bcol * 128 + b_c;

    for (int k0 = 0; k0 < K; k0 += 8) {
        float4 av = *(const float4*)(Ap + k0);
        As[a_c + 0][a_r] = av.x;
        As[a_c + 1][a_r] = av.y;
        As[a_c + 2][a_r] = av.z;
        As[a_c + 3][a_r] = av.w;
        float4 bv = *(const float4*)(Bp + (size_t)k0 * N);
        *(float4*)&Bs[b_k][b_c] = bv;
        __syncthreads();

        #pragma unroll
        for (int kk = 0; kk < 8; kk++) {
            float a[8], bb[8];
            #pragma unroll
            for (int i = 0; i < 8; i++) a[i] = As[kk][ty * 8 + i];
            #pragma unroll
            for (int j = 0; j < 8; j++) bb[j] = Bs[kk][tx * 8 + j];
            #pragma unroll
            for (int i = 0; i < 8; i++)
                #pragma unroll
                for (int j = 0; j < 8; j++)
                    acc[i][j] = fmaf(a[i], bb[j], acc[i][j]);
        }
        __syncthreads();
    }

    #pragma unroll
    for (int i = 0; i < 8; i++) {
        const int gr = brow * 128 + ty * 8 + i;
        const int b_ = gr / NT;
        const int t  = gr - b_ * NT;
        #pragma unroll
        for (int j = 0; j < 8; j++) {
            const int gc = bcol * 128 + tx * 8 + j;
            const float val = acc[i][j] + bias[gc];
            if (MODE == 0) {
                C[(size_t)gr * N + gc] = val;
            } else {
                const int s  = gc / CC;
                const int r  = gc - s * CC;
                const int hh = r >> 6;
                const int d  = r & 63;
                const size_t idx = ((size_t)((b_ * HH + hh) * NT + t)) * DH + d;
                float* dst = (s == 0) ? Cq : (s == 1) ? Ck : Cv;
                dst[idx] = val;
            }
        }
    }
}

// ---------------- attention: one CTA per (b,h) ----------------
__global__ __launch_bounds__(256)
void attn_kernel(const float* __restrict__ q, const float* __restrict__ k,
                 const float* __restrict__ v, float* __restrict__ out)
{
    extern __shared__ float smem[];
    float* kT = smem;                       // [64][KT_STRIDE]
    float* vs = smem + DH * KT_STRIDE;      // [197][64]

    const int bh = blockIdx.x;
    const int b  = bh / HH;
    const int h  = bh - b * HH;
    const size_t base = (size_t)bh * NT * DH;
    const int tid  = threadIdx.x;
    const int lane = tid & 31;
    const int w    = tid >> 5;

    for (int idx = tid; idx < NT * DH; idx += 256) {
        const int t = idx >> 6;
        const int d = idx & 63;
        kT[d * KT_STRIDE + t] = k[base + idx];
        vs[idx] = v[base + idx];
    }
    __syncthreads();

    const float scale = 0.125f;   // 64^-0.5

    for (int cb = 0; cb < NT; cb += 16) {
        const int r0 = cb + w * 2;
        if (r0 < NT) {
            const int r1 = r0 + 1;
            const bool has1 = (r1 < NT);

            const float qA0 = q[base + (size_t)r0 * DH + lane];
            const float qA1 = q[base + (size_t)r0 * DH + 32 + lane];
            const float qB0 = has1 ? q[base + (size_t)r1 * DH + lane] : 0.f;
            const float qB1 = has1 ? q[base + (size_t)r1 * DH + 32 + lane] : 0.f;

            float acc0[7], acc1[7];
            #pragma unroll
            for (int m = 0; m < 7; m++) { acc0[m] = 0.f; acc1[m] = 0.f; }

            // S = q @ kT
            #pragma unroll
            for (int half = 0; half < 2; half++) {
                const float qaS = half ? qA1 : qA0;
                const float qbS = half ? qB1 : qB0;
                for (int kks = 0; kks < 32; kks++) {
                    const float qa = __shfl_sync(0xffffffffu, qaS, kks);
                    const float qb = __shfl_sync(0xffffffffu, qbS, kks);
                    const int kk = half * 32 + kks;
                    const float* kr = &kT[kk * KT_STRIDE + lane];
                    #pragma unroll
                    for (int m = 0; m < 7; m++) {
                        const float kv = kr[32 * m];
                        acc0[m] = fmaf(qa, kv, acc0[m]);
                        acc1[m] = fmaf(qb, kv, acc1[m]);
                    }
                }
            }

            // softmax (rows r0, r1)
            float mx0 = -1e30f, mx1 = -1e30f;
            #pragma unroll
            for (int m = 0; m < 7; m++) {
                const bool valid = (m < 6) || (lane < 5);
                const float s0 = valid ? acc0[m] * scale : -1e30f;
                const float s1 = valid ? acc1[m] * scale : -1e30f;
                acc0[m] = s0; acc1[m] = s1;
                mx0 = fmaxf(mx0, s0); mx1 = fmaxf(mx1, s1);
            }
            #pragma unroll
            for (int off = 16; off > 0; off >>= 1) {
                mx0 = fmaxf(mx0, __shfl_xor_sync(0xffffffffu, mx0, off));
                mx1 = fmaxf(mx1, __shfl_xor_sync(0xffffffffu, mx1, off));
            }
            float sum0 = 0.f, sum1 = 0.f;
            #pragma unroll
            for (int m = 0; m < 7; m++) {
                const float e0 = __expf(acc0[m] - mx0);
                const float e1 = __expf(acc1[m] - mx1);
                acc0[m] = e0; acc1[m] = e1;
                sum0 += e0; sum1 += e1;
            }
            #pragma unroll
            for (int off = 16; off > 0; off >>= 1) {
                sum0 += __shfl_xor_sync(0xffffffffu, sum0, off);
                sum1 += __shfl_xor_sync(0xffffffffu, sum1, off);
            }
            const float inv0 = 1.0f / sum0;
            const float inv1 = 1.0f / sum1;

            // O = P @ V
            float o00 = 0.f, o01 = 0.f, o10 = 0.f, o11 = 0.f;
            #pragma unroll
            for (int m = 0; m < 7; m++) {
                const int lim = (m == 6) ? 5 : 32;
                for (int jj = 0; jj < lim; jj++) {
                    const float p0 = __shfl_sync(0xffffffffu, acc0[m], jj);
                    const float p1 = __shfl_sync(0xffffffffu, acc1[m], jj);
                    const float* vr = &vs[(m * 32 + jj) * DH + lane];
                    const float va = vr[0];
                    const float vb = vr[32];
                    o00 = fmaf(p0, va, o00); o01 = fmaf(p0, vb, o01);
                    o10 = fmaf(p1, va, o10); o11 = fmaf(p1, vb, o11);
                }
            }

            const size_t obase = ((size_t)b * NT + r0) * CC + h * DH;
            out[obase + lane]      = o00 * inv0;
            out[obase + 32 + lane] = o01 * inv0;
            if (has1) {
                out[obase + CC + lane]      = o10 * inv1;
                out[obase + CC + 32 + lane] = o11 * inv1;
            }
        }
    }
}

// ---------------- depthwise 3x3 conv on V (tokens 1:), residual add ----------------
__global__ __launch_bounds__(256)
void dwconv_kernel(const float* __restrict__ v, const float* __restrict__ wgt,
                   const float* __restrict__ bias, float* __restrict__ out)
{
    const int idx = blockIdx.x * 256 + threadIdx.x;
    const int c  = idx % CC;
    const int sp = (idx / CC) % (GRID * GRID);
    const int b  = idx / (CC * GRID * GRID);
    const int y = sp / GRID, x = sp - y * GRID;
    const int hh = c >> 6, d = c & 63;

    const float* vb = v + ((size_t)(b * HH + hh) * NT) * DH + d;
    float s = bias[c];
    #pragma unroll
    for (int ky = 0; ky < 3; ky++) {
        const int yy = y + ky - 1;
        if (yy < 0 || yy >= GRID) continue;
        #pragma unroll
        for (int kx = 0; kx < 3; kx++) {
            const int xx = x + kx - 1;
            if (xx < 0 || xx >= GRID) continue;
            const int t = 1 + yy * GRID + xx;
            s = fmaf(vb[(size_t)t * DH], wgt[c * 9 + ky * 3 + kx], s);
        }
    }
    out[((size_t)b * NT + 1 + sp) * CC + c] += s;
}

// ---------------- launch ----------------
extern "C" void kernel_launch(void* const* d_in, const int* in_sizes, int n_in,
                              void* d_out, int out_size)
{
    const float* x      = (const float*)d_in[0];
    const float* W_qkv  = (const float*)d_in[1];
    const float* b_qkv  = (const float*)d_in[2];
    const float* W_proj = (const float*)d_in[3];
    const float* b_proj = (const float*)d_in[4];
    const float* dwc_w  = (const float*)d_in[5];
    const float* dwc_b  = (const float*)d_in[6];
    float* out = (float*)d_out;

    float *qp, *kp, *vp, *attp;
    cudaGetSymbolAddress((void**)&qp,   g_q);
    cudaGetSymbolAddress((void**)&kp,   g_k);
    cudaGetSymbolAddress((void**)&vp,   g_v);
    cudaGetSymbolAddress((void**)&attp, g_att);

    // 1) qkv projection with scatter into (B,H,N,D) q/k/v
    {
        dim3 grid(3 * CC / 128, M_ROWS / 128);
        sgemm_kernel<1><<<grid, 256>>>(x, W_qkv, b_qkv, nullptr, qp, kp, vp,
                                       M_ROWS, 3 * CC, CC);
    }

    // 2) attention
    {
        const int smem_bytes = (DH * KT_STRIDE + NT * DH) * (int)sizeof(float);
        cudaFuncSetAttribute(attn_kernel, cudaFuncAttributeMaxDynamicSharedMemorySize,
                             smem_bytes);
        attn_kernel<<<Bv * HH, 256, smem_bytes>>>(qp, kp, vp, attp);
    }

    // 3) depthwise conv + residual add into g_att rows 1:
    {
        const int total = Bv * GRID * GRID * CC;
        dwconv_kernel<<<total / 256, 256>>>(vp, dwc_w, dwc_b, attp);
    }

    // 4) output projection
    {
        dim3 grid(CC / 128, M_ROWS / 128);
        sgemm_kernel<0><<<grid, 256>>>(attp, W_proj, b_proj, out,
                                       nullptr, nullptr, nullptr,
                                       M_ROWS, CC, CC);
    }
}

// round 3
// speedup vs baseline: 1.7565x; 1.7565x over previous
#include <cuda_runtime.h>
#include <cuda_bf16.h>
#include <math.h>

#define Bv 256
#define NT 197
#define CC 768
#define HH 12
#define DH 64
#define GRID 14
#define M_ROWS (Bv * NT)          // 50432 = 394*128
#define KT_STRIDE 224

// ---------------- scratch ----------------
__device__ float g_q[(size_t)Bv * HH * NT * DH];
__device__ float g_k[(size_t)Bv * HH * NT * DH];
__device__ float g_v[(size_t)Bv * HH * NT * DH];
__device__ float g_att[(size_t)Bv * NT * CC];

// ---------------- mma helpers ----------------
__device__ __forceinline__ unsigned smem_u32(const void* p) {
    return (unsigned)__cvta_generic_to_shared(p);
}
__device__ __forceinline__ void ldsm_x4(unsigned& r0, unsigned& r1, unsigned& r2, unsigned& r3,
                                        unsigned addr) {
    asm volatile("ldmatrix.sync.aligned.m8n8.x4.shared.b16 {%0,%1,%2,%3}, [%4];\n"
                 : "=r"(r0), "=r"(r1), "=r"(r2), "=r"(r3) : "r"(addr));
}
__device__ __forceinline__ void ldsm_x2t(unsigned& r0, unsigned& r1, unsigned addr) {
    asm volatile("ldmatrix.sync.aligned.m8n8.x2.trans.shared.b16 {%0,%1}, [%2];\n"
                 : "=r"(r0), "=r"(r1) : "r"(addr));
}
__device__ __forceinline__ void mma16816(float* c, unsigned a0, unsigned a1, unsigned a2,
                                         unsigned a3, unsigned b0, unsigned b1) {
    asm volatile("mma.sync.aligned.m16n8k16.row.col.f32.bf16.bf16.f32 "
                 "{%0,%1,%2,%3}, {%4,%5,%6,%7}, {%8,%9}, {%0,%1,%2,%3};\n"
                 : "+f"(c[0]), "+f"(c[1]), "+f"(c[2]), "+f"(c[3])
                 : "r"(a0), "r"(a1), "r"(a2), "r"(a3), "r"(b0), "r"(b1));
}
__device__ __forceinline__ void split_store4(__nv_bfloat16* hp, __nv_bfloat16* lp, float4 v) {
    __nv_bfloat162 h0, h1, l0, l1;
    h0.x = __float2bfloat16_rn(v.x); l0.x = __float2bfloat16_rn(v.x - __bfloat162float(h0.x));
    h0.y = __float2bfloat16_rn(v.y); l0.y = __float2bfloat16_rn(v.y - __bfloat162float(h0.y));
    h1.x = __float2bfloat16_rn(v.z); l1.x = __float2bfloat16_rn(v.z - __bfloat162float(h1.x));
    h1.y = __float2bfloat16_rn(v.w); l1.y = __float2bfloat16_rn(v.w - __bfloat162float(h1.y));
    reinterpret_cast<__nv_bfloat162*>(hp)[0] = h0;
    reinterpret_cast<__nv_bfloat162*>(hp)[1] = h1;
    reinterpret_cast<__nv_bfloat162*>(lp)[0] = l0;
    reinterpret_cast<__nv_bfloat162*>(lp)[1] = l1;
}

// ---------------- bf16x3 tensor-core GEMM: 128x128x32 CTA, 256 threads ----------------
// MODE 0: C[m*N+n] = acc + bias[n]
// MODE 1: qkv scatter into g_q/g_k/g_v with layout (B,H,N,D)
#define LDA 40    // 32 + 8 pad (bf16), row stride 80B: 16B-aligned, LDSM conflict-free
#define LDB 136   // 128 + 8 pad, row stride 272B: 16B-aligned, conflict-free

template<int MODE>
__global__ __launch_bounds__(256, 2)
void mma_gemm(const float* __restrict__ A, const float* __restrict__ Bm,
              const float* __restrict__ bias, float* __restrict__ C,
              float* __restrict__ Cq, float* __restrict__ Ck, float* __restrict__ Cv,
              int M, int N, int K)
{
    __shared__ alignas(16) __nv_bfloat16 Ah[128][LDA];
    __shared__ alignas(16) __nv_bfloat16 Al[128][LDA];
    __shared__ alignas(16) __nv_bfloat16 Bh[32][LDB];
    __shared__ alignas(16) __nv_bfloat16 Bl[32][LDB];

    const int tid  = threadIdx.x;
    const int brow = blockIdx.y;
    const int bcol = blockIdx.x;
    const int lane = tid & 31;
    const int wid  = tid >> 5;
    const int wm = (wid & 1) * 64;   // warp m-offset within 128
    const int wn = (wid >> 1) * 32;  // warp n-offset within 128

    float acc[4][4][4];
    #pragma unroll
    for (int mt = 0; mt < 4; mt++)
        #pragma unroll
        for (int nt = 0; nt < 4; nt++)
            #pragma unroll
            for (int e = 0; e < 4; e++) acc[mt][nt][e] = 0.f;

    // staging mapping
    const int ar = tid >> 1;            // 0..127
    const int ac = (tid & 1) << 4;      // 0 or 16
    const int br = tid >> 3;            // 0..31
    const int bc = (tid & 7) << 4;      // 0..112
    const float* Ap = A + (size_t)(brow * 128 + ar) * K + ac;
    const float* Bp = Bm + (size_t)br * N + bcol * 128 + bc;

    const unsigned aBaseH = smem_u32(&Ah[0][0]);
    const unsigned aBaseL = smem_u32(&Al[0][0]);
    const unsigned bBaseH = smem_u32(&Bh[0][0]);
    const unsigned bBaseL = smem_u32(&Bl[0][0]);

    const int aRowLane = lane & 15;
    const int aColLane = (lane >> 4) << 3;
    const int bRowLane = lane & 15;

    for (int k0 = 0; k0 < K; k0 += 32) {
        #pragma unroll
        for (int v = 0; v < 4; v++) {
            float4 a4 = *(const float4*)(Ap + k0 + v * 4);
            split_store4(&Ah[ar][ac + v * 4], &Al[ar][ac + v * 4], a4);
            float4 b4 = *(const float4*)(Bp + (size_t)k0 * N + v * 4);
            split_store4(&Bh[br][bc + v * 4], &Bl[br][bc + v * 4], b4);
        }
        __syncthreads();

        #pragma unroll
        for (int ks = 0; ks < 2; ks++) {
            unsigned bhf[4][2], blf[4][2];
            #pragma unroll
            for (int nt = 0; nt < 4; nt++) {
                const unsigned boff = ((ks * 16 + bRowLane) * LDB + wn + nt * 8) * 2;
                ldsm_x2t(bhf[nt][0], bhf[nt][1], bBaseH + boff);
                ldsm_x2t(blf[nt][0], blf[nt][1], bBaseL + boff);
            }
            #pragma unroll
            for (int mt = 0; mt < 4; mt++) {
                const unsigned aoff = ((wm + mt * 16 + aRowLane) * LDA + ks * 16 + aColLane) * 2;
                unsigned ah0, ah1, ah2, ah3, al0, al1, al2, al3;
                ldsm_x4(ah0, ah1, ah2, ah3, aBaseH + aoff);
                ldsm_x4(al0, al1, al2, al3, aBaseL + aoff);
                #pragma unroll
                for (int nt = 0; nt < 4; nt++) {
                    mma16816(acc[mt][nt], ah0, ah1, ah2, ah3, bhf[nt][0], bhf[nt][1]);
                    mma16816(acc[mt][nt], al0, al1, al2, al3, bhf[nt][0], bhf[nt][1]);
                    mma16816(acc[mt][nt], ah0, ah1, ah2, ah3, blf[nt][0], blf[nt][1]);
                }
            }
        }
        __syncthreads();
    }

    // epilogue
    const int trow = lane >> 2;
    const int tcol = (lane & 3) << 1;
    #pragma unroll
    for (int mt = 0; mt < 4; mt++) {
        #pragma unroll
        for (int nt = 0; nt < 4; nt++) {
            const int gc = bcol * 128 + wn + nt * 8 + tcol;
            const float bia0 = bias[gc];
            const float bia1 = bias[gc + 1];
            #pragma unroll
            for (int half = 0; half < 2; half++) {
                const int gr = brow * 128 + wm + mt * 16 + trow + half * 8;
                float2 val;
                val.x = acc[mt][nt][half * 2 + 0] + bia0;
                val.y = acc[mt][nt][half * 2 + 1] + bia1;
                if (MODE == 0) {
                    *(float2*)&C[(size_t)gr * N + gc] = val;
                } else {
                    const int b_ = gr / NT;
                    const int t  = gr - b_ * NT;
                    const int s  = gc / CC;
                    const int r  = gc - s * CC;
                    const int hh = r >> 6;
                    const int d  = r & 63;
                    const size_t idx = ((size_t)((b_ * HH + hh) * NT + t)) * DH + d;
                    float* dst = (s == 0) ? Cq : (s == 1) ? Ck : Cv;
                    *(float2*)&dst[idx] = val;
                }
            }
        }
    }
}

// ---------------- attention: one CTA per (b,h) ----------------
__global__ __launch_bounds__(256)
void attn_kernel(const float* __restrict__ q, const float* __restrict__ k,
                 const float* __restrict__ v, float* __restrict__ out)
{
    extern __shared__ float smem[];
    float* kT = smem;                       // [64][KT_STRIDE]
    float* vs = smem + DH * KT_STRIDE;      // [197][64]

    const int bh = blockIdx.x;
    const int b  = bh / HH;
    const int h  = bh - b * HH;
    const size_t base = (size_t)bh * NT * DH;
    const int tid  = threadIdx.x;
    const int lane = tid & 31;
    const int w    = tid >> 5;

    for (int idx = tid; idx < NT * DH; idx += 256) {
        const int t = idx >> 6;
        const int d = idx & 63;
        kT[d * KT_STRIDE + t] = k[base + idx];
        vs[idx] = v[base + idx];
    }
    __syncthreads();

    const float scale = 0.125f;   // 64^-0.5

    for (int cb = 0; cb < NT; cb += 16) {
        const int r0 = cb + w * 2;
        if (r0 < NT) {
            const int r1 = r0 + 1;
            const bool has1 = (r1 < NT);

            const float qA0 = q[base + (size_t)r0 * DH + lane];
            const float qA1 = q[base + (size_t)r0 * DH + 32 + lane];
            const float qB0 = has1 ? q[base + (size_t)r1 * DH + lane] : 0.f;
            const float qB1 = has1 ? q[base + (size_t)r1 * DH + 32 + lane] : 0.f;

            float acc0[7], acc1[7];
            #pragma unroll
            for (int m = 0; m < 7; m++) { acc0[m] = 0.f; acc1[m] = 0.f; }

            #pragma unroll
            for (int half = 0; half < 2; half++) {
                const float qaS = half ? qA1 : qA0;
                const float qbS = half ? qB1 : qB0;
                for (int kks = 0; kks < 32; kks++) {
                    const float qa = __shfl_sync(0xffffffffu, qaS, kks);
                    const float qb = __shfl_sync(0xffffffffu, qbS, kks);
                    const int kk = half * 32 + kks;
                    const float* kr = &kT[kk * KT_STRIDE + lane];
                    #pragma unroll
                    for (int m = 0; m < 7; m++) {
                        const float kv = kr[32 * m];
                        acc0[m] = fmaf(qa, kv, acc0[m]);
                        acc1[m] = fmaf(qb, kv, acc1[m]);
                    }
                }
            }

            float mx0 = -1e30f, mx1 = -1e30f;
            #pragma unroll
            for (int m = 0; m < 7; m++) {
                const bool valid = (m < 6) || (lane < 5);
                const float s0 = valid ? acc0[m] * scale : -1e30f;
                const float s1 = valid ? acc1[m] * scale : -1e30f;
                acc0[m] = s0; acc1[m] = s1;
                mx0 = fmaxf(mx0, s0); mx1 = fmaxf(mx1, s1);
            }
            #pragma unroll
            for (int off = 16; off > 0; off >>= 1) {
                mx0 = fmaxf(mx0, __shfl_xor_sync(0xffffffffu, mx0, off));
                mx1 = fmaxf(mx1, __shfl_xor_sync(0xffffffffu, mx1, off));
            }
            float sum0 = 0.f, sum1 = 0.f;
            #pragma unroll
            for (int m = 0; m < 7; m++) {
                const float e0 = __expf(acc0[m] - mx0);
                const float e1 = __expf(acc1[m] - mx1);
                acc0[m] = e0; acc1[m] = e1;
                sum0 += e0; sum1 += e1;
            }
            #pragma unroll
            for (int off = 16; off > 0; off >>= 1) {
                sum0 += __shfl_xor_sync(0xffffffffu, sum0, off);
                sum1 += __shfl_xor_sync(0xffffffffu, sum1, off);
            }
            const float inv0 = 1.0f / sum0;
            const float inv1 = 1.0f / sum1;

            float o00 = 0.f, o01 = 0.f, o10 = 0.f, o11 = 0.f;
            #pragma unroll
            for (int m = 0; m < 7; m++) {
                const int lim = (m == 6) ? 5 : 32;
                for (int jj = 0; jj < lim; jj++) {
                    const float p0 = __shfl_sync(0xffffffffu, acc0[m], jj);
                    const float p1 = __shfl_sync(0xffffffffu, acc1[m], jj);
                    const float* vr = &vs[(m * 32 + jj) * DH + lane];
                    const float va = vr[0];
                    const float vb = vr[32];
                    o00 = fmaf(p0, va, o00); o01 = fmaf(p0, vb, o01);
                    o10 = fmaf(p1, va, o10); o11 = fmaf(p1, vb, o11);
                }
            }

            const size_t obase = ((size_t)b * NT + r0) * CC + h * DH;
            out[obase + lane]      = o00 * inv0;
            out[obase + 32 + lane] = o01 * inv0;
            if (has1) {
                out[obase + CC + lane]      = o10 * inv1;
                out[obase + CC + 32 + lane] = o11 * inv1;
            }
        }
    }
}

// ---------------- depthwise 3x3 conv on V (tokens 1:), residual add ----------------
__global__ __launch_bounds__(256)
void dwconv_kernel(const float* __restrict__ v, const float* __restrict__ wgt,
                   const float* __restrict__ bias, float* __restrict__ out)
{
    const int idx = blockIdx.x * 256 + threadIdx.x;
    const int c  = idx % CC;
    const int sp = (idx / CC) % (GRID * GRID);
    const int b  = idx / (CC * GRID * GRID);
    const int y = sp / GRID, x = sp - y * GRID;
    const int hh = c >> 6, d = c & 63;

    const float* vb = v + ((size_t)(b * HH + hh) * NT) * DH + d;
    float s = bias[c];
    #pragma unroll
    for (int ky = 0; ky < 3; ky++) {
        const int yy = y + ky - 1;
        if (yy < 0 || yy >= GRID) continue;
        #pragma unroll
        for (int kx = 0; kx < 3; kx++) {
            const int xx = x + kx - 1;
            if (xx < 0 || xx >= GRID) continue;
            const int t = 1 + yy * GRID + xx;
            s = fmaf(vb[(size_t)t * DH], wgt[c * 9 + ky * 3 + kx], s);
        }
    }
    out[((size_t)b * NT + 1 + sp) * CC + c] += s;
}

// ---------------- launch ----------------
extern "C" void kernel_launch(void* const* d_in, const int* in_sizes, int n_in,
                              void* d_out, int out_size)
{
    const float* x      = (const float*)d_in[0];
    const float* W_qkv  = (const float*)d_in[1];
    const float* b_qkv  = (const float*)d_in[2];
    const float* W_proj = (const float*)d_in[3];
    const float* b_proj = (const float*)d_in[4];
    const float* dwc_w  = (const float*)d_in[5];
    const float* dwc_b  = (const float*)d_in[6];
    float* out = (float*)d_out;

    float *qp, *kp, *vp, *attp;
    cudaGetSymbolAddress((void**)&qp,   g_q);
    cudaGetSymbolAddress((void**)&kp,   g_k);
    cudaGetSymbolAddress((void**)&vp,   g_v);
    cudaGetSymbolAddress((void**)&attp, g_att);

    // 1) qkv projection (bf16x3 tensor cores) with scatter into (B,H,N,D)
    {
        dim3 grid(3 * CC / 128, M_ROWS / 128);
        mma_gemm<1><<<grid, 256>>>(x, W_qkv, b_qkv, nullptr, qp, kp, vp,
                                   M_ROWS, 3 * CC, CC);
    }

    // 2) attention
    {
        const int smem_bytes = (DH * KT_STRIDE + NT * DH) * (int)sizeof(float);
        cudaFuncSetAttribute(attn_kernel, cudaFuncAttributeMaxDynamicSharedMemorySize,
                             smem_bytes);
        attn_kernel<<<Bv * HH, 256, smem_bytes>>>(qp, kp, vp, attp);
    }

    // 3) depthwise conv + residual add into g_att rows 1:
    {
        const int total = Bv * GRID * GRID * CC;
        dwconv_kernel<<<total / 256, 256>>>(vp, dwc_w, dwc_b, attp);
    }

    // 4) output projection (bf16x3 tensor cores)
    {
        dim3 grid(CC / 128, M_ROWS / 128);
        mma_gemm<0><<<grid, 256>>>(attp, W_proj, b_proj, out,
                                   nullptr, nullptr, nullptr,
                                   M_ROWS, CC, CC);
    }
}

// round 4
// speedup vs baseline: 2.2659x; 1.2900x over previous
#include <cuda_runtime.h>
#include <cuda_bf16.h>
#include <math.h>

#define Bv 256
#define NT 197
#define CC 768
#define HH 12
#define DH 64
#define GRID 14
#define M_ROWS (Bv * NT)          // 50432 = 394*128

// ---------------- scratch ----------------
__device__ float g_q[(size_t)Bv * HH * NT * DH];
__device__ float g_k[(size_t)Bv * HH * NT * DH];
__device__ float g_v[(size_t)Bv * HH * NT * DH];
__device__ float g_att[(size_t)Bv * NT * CC];

// ---------------- mma helpers ----------------
__device__ __forceinline__ unsigned smem_u32(const void* p) {
    return (unsigned)__cvta_generic_to_shared(p);
}
__device__ __forceinline__ void ldsm_x4(unsigned& r0, unsigned& r1, unsigned& r2, unsigned& r3,
                                        unsigned addr) {
    asm volatile("ldmatrix.sync.aligned.m8n8.x4.shared.b16 {%0,%1,%2,%3}, [%4];\n"
                 : "=r"(r0), "=r"(r1), "=r"(r2), "=r"(r3) : "r"(addr));
}
__device__ __forceinline__ void ldsm_x4t(unsigned& r0, unsigned& r1, unsigned& r2, unsigned& r3,
                                         unsigned addr) {
    asm volatile("ldmatrix.sync.aligned.m8n8.x4.trans.shared.b16 {%0,%1,%2,%3}, [%4];\n"
                 : "=r"(r0), "=r"(r1), "=r"(r2), "=r"(r3) : "r"(addr));
}
__device__ __forceinline__ void ldsm_x2t(unsigned& r0, unsigned& r1, unsigned addr) {
    asm volatile("ldmatrix.sync.aligned.m8n8.x2.trans.shared.b16 {%0,%1}, [%2];\n"
                 : "=r"(r0), "=r"(r1) : "r"(addr));
}
__device__ __forceinline__ void mma16816(float* c, unsigned a0, unsigned a1, unsigned a2,
                                         unsigned a3, unsigned b0, unsigned b1) {
    asm volatile("mma.sync.aligned.m16n8k16.row.col.f32.bf16.bf16.f32 "
                 "{%0,%1,%2,%3}, {%4,%5,%6,%7}, {%8,%9}, {%0,%1,%2,%3};\n"
                 : "+f"(c[0]), "+f"(c[1]), "+f"(c[2]), "+f"(c[3])
                 : "r"(a0), "r"(a1), "r"(a2), "r"(a3), "r"(b0), "r"(b1));
}
__device__ __forceinline__ void split_store4(__nv_bfloat16* hp, __nv_bfloat16* lp, float4 v) {
    __nv_bfloat162 h0, h1, l0, l1;
    h0.x = __float2bfloat16_rn(v.x); l0.x = __float2bfloat16_rn(v.x - __bfloat162float(h0.x));
    h0.y = __float2bfloat16_rn(v.y); l0.y = __float2bfloat16_rn(v.y - __bfloat162float(h0.y));
    h1.x = __float2bfloat16_rn(v.z); l1.x = __float2bfloat16_rn(v.z - __bfloat162float(h1.x));
    h1.y = __float2bfloat16_rn(v.w); l1.y = __float2bfloat16_rn(v.w - __bfloat162float(h1.y));
    reinterpret_cast<__nv_bfloat162*>(hp)[0] = h0;
    reinterpret_cast<__nv_bfloat162*>(hp)[1] = h1;
    reinterpret_cast<__nv_bfloat162*>(lp)[0] = l0;
    reinterpret_cast<__nv_bfloat162*>(lp)[1] = l1;
}
__device__ __forceinline__ unsigned pack_hi(float x, float y) {
    __nv_bfloat162 t;
    t.x = __float2bfloat16_rn(x);
    t.y = __float2bfloat16_rn(y);
    return *reinterpret_cast<unsigned*>(&t);
}
__device__ __forceinline__ unsigned pack_lo(float x, float y) {
    __nv_bfloat162 t;
    __nv_bfloat16 hx = __float2bfloat16_rn(x);
    __nv_bfloat16 hy = __float2bfloat16_rn(y);
    t.x = __float2bfloat16_rn(x - __bfloat162float(hx));
    t.y = __float2bfloat16_rn(y - __bfloat162float(hy));
    return *reinterpret_cast<unsigned*>(&t);
}

// ---------------- bf16x3 tensor-core GEMM: 128x128x32 CTA, 256 threads ----------------
#define LDA 40    // 32 + 8 pad (bf16)
#define LDB 136   // 128 + 8 pad

template<int MODE>
__global__ __launch_bounds__(256, 2)
void mma_gemm(const float* __restrict__ A, const float* __restrict__ Bm,
              const float* __restrict__ bias, float* __restrict__ C,
              float* __restrict__ Cq, float* __restrict__ Ck, float* __restrict__ Cv,
              int M, int N, int K)
{
    __shared__ alignas(16) __nv_bfloat16 Ah[128][LDA];
    __shared__ alignas(16) __nv_bfloat16 Al[128][LDA];
    __shared__ alignas(16) __nv_bfloat16 Bh[32][LDB];
    __shared__ alignas(16) __nv_bfloat16 Bl[32][LDB];

    const int tid  = threadIdx.x;
    const int brow = blockIdx.y;
    const int bcol = blockIdx.x;
    const int lane = tid & 31;
    const int wid  = tid >> 5;
    const int wm = (wid & 1) * 64;
    const int wn = (wid >> 1) * 32;

    float acc[4][4][4];
    #pragma unroll
    for (int mt = 0; mt < 4; mt++)
        #pragma unroll
        for (int nt = 0; nt < 4; nt++)
            #pragma unroll
            for (int e = 0; e < 4; e++) acc[mt][nt][e] = 0.f;

    const int ar = tid >> 1;
    const int ac = (tid & 1) << 4;
    const int br = tid >> 3;
    const int bc = (tid & 7) << 4;
    const float* Ap = A + (size_t)(brow * 128 + ar) * K + ac;
    const float* Bp = Bm + (size_t)br * N + bcol * 128 + bc;

    const unsigned aBaseH = smem_u32(&Ah[0][0]);
    const unsigned aBaseL = smem_u32(&Al[0][0]);
    const unsigned bBaseH = smem_u32(&Bh[0][0]);
    const unsigned bBaseL = smem_u32(&Bl[0][0]);

    const int aRowLane = lane & 15;
    const int aColLane = (lane >> 4) << 3;
    const int bRowLane = lane & 15;

    for (int k0 = 0; k0 < K; k0 += 32) {
        #pragma unroll
        for (int v = 0; v < 4; v++) {
            float4 a4 = *(const float4*)(Ap + k0 + v * 4);
            split_store4(&Ah[ar][ac + v * 4], &Al[ar][ac + v * 4], a4);
            float4 b4 = *(const float4*)(Bp + (size_t)k0 * N + v * 4);
            split_store4(&Bh[br][bc + v * 4], &Bl[br][bc + v * 4], b4);
        }
        __syncthreads();

        #pragma unroll
        for (int ks = 0; ks < 2; ks++) {
            unsigned bhf[4][2], blf[4][2];
            #pragma unroll
            for (int nt = 0; nt < 4; nt++) {
                const unsigned boff = ((ks * 16 + bRowLane) * LDB + wn + nt * 8) * 2;
                ldsm_x2t(bhf[nt][0], bhf[nt][1], bBaseH + boff);
                ldsm_x2t(blf[nt][0], blf[nt][1], bBaseL + boff);
            }
            #pragma unroll
            for (int mt = 0; mt < 4; mt++) {
                const unsigned aoff = ((wm + mt * 16 + aRowLane) * LDA + ks * 16 + aColLane) * 2;
                unsigned ah0, ah1, ah2, ah3, al0, al1, al2, al3;
                ldsm_x4(ah0, ah1, ah2, ah3, aBaseH + aoff);
                ldsm_x4(al0, al1, al2, al3, aBaseL + aoff);
                #pragma unroll
                for (int nt = 0; nt < 4; nt++) {
                    mma16816(acc[mt][nt], ah0, ah1, ah2, ah3, bhf[nt][0], bhf[nt][1]);
                    mma16816(acc[mt][nt], al0, al1, al2, al3, bhf[nt][0], bhf[nt][1]);
                    mma16816(acc[mt][nt], ah0, ah1, ah2, ah3, blf[nt][0], blf[nt][1]);
                }
            }
        }
        __syncthreads();
    }

    const int trow = lane >> 2;
    const int tcol = (lane & 3) << 1;
    #pragma unroll
    for (int mt = 0; mt < 4; mt++) {
        #pragma unroll
        for (int nt = 0; nt < 4; nt++) {
            const int gc = bcol * 128 + wn + nt * 8 + tcol;
            const float bia0 = bias[gc];
            const float bia1 = bias[gc + 1];
            #pragma unroll
            for (int half = 0; half < 2; half++) {
                const int gr = brow * 128 + wm + mt * 16 + trow + half * 8;
                float2 val;
                val.x = acc[mt][nt][half * 2 + 0] + bia0;
                val.y = acc[mt][nt][half * 2 + 1] + bia1;
                if (MODE == 0) {
                    *(float2*)&C[(size_t)gr * N + gc] = val;
                } else {
                    const int b_ = gr / NT;
                    const int t  = gr - b_ * NT;
                    const int s  = gc / CC;
                    const int r  = gc - s * CC;
                    const int hh = r >> 6;
                    const int d  = r & 63;
                    const size_t idx = ((size_t)((b_ * HH + hh) * NT + t)) * DH + d;
                    float* dst = (s == 0) ? Cq : (s == 1) ? Ck : Cv;
                    *(float2*)&dst[idx] = val;
                }
            }
        }
    }
}

// ---------------- tensor-core attention: one CTA per (b,h), 256 threads ----------------
// SMEM bf16 arrays [208][72]: Qh Ql Kh Kl Vh Vl. Q pre-scaled by 0.125.
#define ATT_ROWS 208
#define ATT_LD 72
#define ATT_ELEMS (ATT_ROWS * ATT_LD)   // 14976

__global__ __launch_bounds__(256, 1)
void attn_mma_kernel(const float* __restrict__ q, const float* __restrict__ k,
                     const float* __restrict__ v, float* __restrict__ out)
{
    extern __shared__ __nv_bfloat16 sm[];
    __nv_bfloat16* smQH = sm;
    __nv_bfloat16* smQL = sm + ATT_ELEMS;
    __nv_bfloat16* smKH = sm + 2 * ATT_ELEMS;
    __nv_bfloat16* smKL = sm + 3 * ATT_ELEMS;
    __nv_bfloat16* smVH = sm + 4 * ATT_ELEMS;
    __nv_bfloat16* smVL = sm + 5 * ATT_ELEMS;

    const int bh = blockIdx.x;
    const int b  = bh / HH;
    const int h  = bh - b * HH;
    const size_t base = (size_t)bh * NT * DH;
    const int tid  = threadIdx.x;
    const int lane = tid & 31;
    const int wid  = tid >> 5;

    // ---- stage Q (scaled), K, V as bf16 hi/lo ----
    for (int s5 = tid; s5 < ATT_ROWS * 16; s5 += 256) {
        const int row = s5 >> 4;
        const int c4  = (s5 & 15) << 2;
        float4 qv, kv, vv;
        if (row < NT) {
            qv = *(const float4*)(q + base + (size_t)row * DH + c4);
            kv = *(const float4*)(k + base + (size_t)row * DH + c4);
            vv = *(const float4*)(v + base + (size_t)row * DH + c4);
            qv.x *= 0.125f; qv.y *= 0.125f; qv.z *= 0.125f; qv.w *= 0.125f;
        } else {
            qv = make_float4(0.f, 0.f, 0.f, 0.f);
            kv = qv; vv = qv;
        }
        const int off = row * ATT_LD + c4;
        split_store4(&smQH[off], &smQL[off], qv);
        split_store4(&smKH[off], &smKL[off], kv);
        split_store4(&smVH[off], &smVL[off], vv);
    }
    __syncthreads();

    const unsigned uQH = smem_u32(smQH);
    const unsigned uQL = smem_u32(smQL);
    const unsigned uKH = smem_u32(smKH);
    const unsigned uKL = smem_u32(smKL);
    const unsigned uVH = smem_u32(smVH);
    const unsigned uVL = smem_u32(smVL);

    // 13 m-tiles of 16 rows, warp w handles tiles w, w+8
    for (int mt = wid; mt < 13; mt += 8) {
        const int m0 = mt * 16;

        // Q fragments (4 k-steps)
        unsigned qh[4][4], ql[4][4];
        {
            const int r  = m0 + (lane & 15);
            const int cb = (lane >> 4) << 3;
            #pragma unroll
            for (int ks = 0; ks < 4; ks++) {
                const unsigned off = (unsigned)((r * ATT_LD + ks * 16 + cb) * 2);
                ldsm_x4(qh[ks][0], qh[ks][1], qh[ks][2], qh[ks][3], uQH + off);
                ldsm_x4(ql[ks][0], ql[ks][1], ql[ks][2], ql[ks][3], uQL + off);
            }
        }

        // ---- S = Q K^T (25 n-tiles over 200 cols) ----
        float s[25][4];
        #pragma unroll
        for (int nt = 0; nt < 25; nt++)
            #pragma unroll
            for (int e = 0; e < 4; e++) s[nt][e] = 0.f;

        const int krow = lane & 7;
        const int kcol = ((lane >> 3) & 3) << 3;   // 0,8,16,24
        #pragma unroll 5
        for (int nt = 0; nt < 25; nt++) {
            const int n0 = nt * 8;
            unsigned kh[4][2], kl[4][2];
            {
                const unsigned o1 = (unsigned)(((n0 + krow) * ATT_LD + kcol) * 2);
                unsigned r0, r1, r2, r3;
                ldsm_x4(r0, r1, r2, r3, uKH + o1);
                kh[0][0] = r0; kh[0][1] = r1; kh[1][0] = r2; kh[1][1] = r3;
                ldsm_x4(r0, r1, r2, r3, uKH + o1 + 64);   // +32 bf16
                kh[2][0] = r0; kh[2][1] = r1; kh[3][0] = r2; kh[3][1] = r3;
                ldsm_x4(r0, r1, r2, r3, uKL + o1);
                kl[0][0] = r0; kl[0][1] = r1; kl[1][0] = r2; kl[1][1] = r3;
                ldsm_x4(r0, r1, r2, r3, uKL + o1 + 64);
                kl[2][0] = r0; kl[2][1] = r1; kl[3][0] = r2; kl[3][1] = r3;
            }
            #pragma unroll
            for (int ks = 0; ks < 4; ks++) {
                mma16816(s[nt], qh[ks][0], qh[ks][1], qh[ks][2], qh[ks][3], kh[ks][0], kh[ks][1]);
                mma16816(s[nt], ql[ks][0], ql[ks][1], ql[ks][2], ql[ks][3], kh[ks][0], kh[ks][1]);
                mma16816(s[nt], qh[ks][0], qh[ks][1], qh[ks][2], qh[ks][3], kl[ks][0], kl[ks][1]);
            }
        }

        // ---- softmax ----
        {
            const int col0 = 192 + ((lane & 3) << 1);
            if (col0     >= NT) { s[24][0] = -1e30f; s[24][2] = -1e30f; }
            if (col0 + 1 >= NT) { s[24][1] = -1e30f; s[24][3] = -1e30f; }
        }
        float mx0 = -1e30f, mx1 = -1e30f;
        #pragma unroll
        for (int nt = 0; nt < 25; nt++) {
            mx0 = fmaxf(mx0, fmaxf(s[nt][0], s[nt][1]));
            mx1 = fmaxf(mx1, fmaxf(s[nt][2], s[nt][3]));
        }
        mx0 = fmaxf(mx0, __shfl_xor_sync(0xffffffffu, mx0, 1));
        mx0 = fmaxf(mx0, __shfl_xor_sync(0xffffffffu, mx0, 2));
        mx1 = fmaxf(mx1, __shfl_xor_sync(0xffffffffu, mx1, 1));
        mx1 = fmaxf(mx1, __shfl_xor_sync(0xffffffffu, mx1, 2));

        float sum0 = 0.f, sum1 = 0.f;
        #pragma unroll
        for (int nt = 0; nt < 25; nt++) {
            const float e0 = __expf(s[nt][0] - mx0);
            const float e1 = __expf(s[nt][1] - mx0);
            const float e2 = __expf(s[nt][2] - mx1);
            const float e3 = __expf(s[nt][3] - mx1);
            s[nt][0] = e0; s[nt][1] = e1; s[nt][2] = e2; s[nt][3] = e3;
            sum0 += e0 + e1; sum1 += e2 + e3;
        }
        sum0 += __shfl_xor_sync(0xffffffffu, sum0, 1);
        sum0 += __shfl_xor_sync(0xffffffffu, sum0, 2);
        sum1 += __shfl_xor_sync(0xffffffffu, sum1, 1);
        sum1 += __shfl_xor_sync(0xffffffffu, sum1, 2);
        const float inv0 = 1.0f / sum0;
        const float inv1 = 1.0f / sum1;

        // ---- pack P hi/lo ----
        unsigned phA[25], phB[25], plA[25], plB[25];
        #pragma unroll
        for (int nt = 0; nt < 25; nt++) {
            phA[nt] = pack_hi(s[nt][0], s[nt][1]);
            plA[nt] = pack_lo(s[nt][0], s[nt][1]);
            phB[nt] = pack_hi(s[nt][2], s[nt][3]);
            plB[nt] = pack_lo(s[nt][2], s[nt][3]);
        }

        // ---- O = P V ----
        float o[8][4];
        #pragma unroll
        for (int nt = 0; nt < 8; nt++)
            #pragma unroll
            for (int e = 0; e < 4; e++) o[nt][e] = 0.f;

        const int vrow = ((lane >> 3) & 1) * 8 + (lane & 7);
        const int vcol = (lane >> 4) << 3;
        #pragma unroll 1
        for (int ks = 0; ks < 13; ks++) {
            unsigned ah0, ah1, ah2, ah3, al0, al1, al2, al3;
            if (ks < 12) {
                ah0 = phA[2 * ks];     ah1 = phB[2 * ks];
                ah2 = phA[2 * ks + 1]; ah3 = phB[2 * ks + 1];
                al0 = plA[2 * ks];     al1 = plB[2 * ks];
                al2 = plA[2 * ks + 1]; al3 = plB[2 * ks + 1];
            } else {
                ah0 = phA[24]; ah1 = phB[24]; ah2 = 0u; ah3 = 0u;
                al0 = plA[24]; al1 = plB[24]; al2 = 0u; al3 = 0u;
            }
            const int k0 = ks * 16;
            #pragma unroll
            for (int np = 0; np < 4; np++) {
                const unsigned off = (unsigned)(((k0 + vrow) * ATT_LD + np * 16 + vcol) * 2);
                unsigned vh0, vh1, vh2, vh3, vl0, vl1, vl2, vl3;
                ldsm_x4t(vh0, vh1, vh2, vh3, uVH + off);
                ldsm_x4t(vl0, vl1, vl2, vl3, uVL + off);
                mma16816(o[2 * np],     ah0, ah1, ah2, ah3, vh0, vh1);
                mma16816(o[2 * np],     al0, al1, al2, al3, vh0, vh1);
                mma16816(o[2 * np],     ah0, ah1, ah2, ah3, vl0, vl1);
                mma16816(o[2 * np + 1], ah0, ah1, ah2, ah3, vh2, vh3);
                mma16816(o[2 * np + 1], al0, al1, al2, al3, vh2, vh3);
                mma16816(o[2 * np + 1], ah0, ah1, ah2, ah3, vl2, vl3);
            }
        }

        // ---- store ----
        const int r0 = m0 + (lane >> 2);
        const int r1 = r0 + 8;
        const int cb = h * DH + ((lane & 3) << 1);
        if (r0 < NT) {
            float* op = out + ((size_t)b * NT + r0) * CC + cb;
            #pragma unroll
            for (int nt = 0; nt < 8; nt++) {
                float2 val; val.x = o[nt][0] * inv0; val.y = o[nt][1] * inv0;
                *(float2*)(op + nt * 8) = val;
            }
        }
        if (r1 < NT) {
            float* op = out + ((size_t)b * NT + r1) * CC + cb;
            #pragma unroll
            for (int nt = 0; nt < 8; nt++) {
                float2 val; val.x = o[nt][2] * inv1; val.y = o[nt][3] * inv1;
                *(float2*)(op + nt * 8) = val;
            }
        }
    }
}

// ---------------- depthwise 3x3 conv on V (tokens 1:), residual add ----------------
__global__ __launch_bounds__(256)
void dwconv_kernel(const float* __restrict__ v, const float* __restrict__ wgt,
                   const float* __restrict__ bias, float* __restrict__ out)
{
    const int idx = blockIdx.x * 256 + threadIdx.x;
    const int c  = idx % CC;
    const int sp = (idx / CC) % (GRID * GRID);
    const int b  = idx / (CC * GRID * GRID);
    const int y = sp / GRID, x = sp - y * GRID;
    const int hh = c >> 6, d = c & 63;

    const float* vb = v + ((size_t)(b * HH + hh) * NT) * DH + d;
    float s = bias[c];
    #pragma unroll
    for (int ky = 0; ky < 3; ky++) {
        const int yy = y + ky - 1;
        if (yy < 0 || yy >= GRID) continue;
        #pragma unroll
        for (int kx = 0; kx < 3; kx++) {
            const int xx = x + kx - 1;
            if (xx < 0 || xx >= GRID) continue;
            const int t = 1 + yy * GRID + xx;
            s = fmaf(vb[(size_t)t * DH], wgt[c * 9 + ky * 3 + kx], s);
        }
    }
    out[((size_t)b * NT + 1 + sp) * CC + c] += s;
}

// ---------------- launch ----------------
extern "C" void kernel_launch(void* const* d_in, const int* in_sizes, int n_in,
                              void* d_out, int out_size)
{
    const float* x      = (const float*)d_in[0];
    const float* W_qkv  = (const float*)d_in[1];
    const float* b_qkv  = (const float*)d_in[2];
    const float* W_proj = (const float*)d_in[3];
    const float* b_proj = (const float*)d_in[4];
    const float* dwc_w  = (const float*)d_in[5];
    const float* dwc_b  = (const float*)d_in[6];
    float* out = (float*)d_out;

    float *qp, *kp, *vp, *attp;
    cudaGetSymbolAddress((void**)&qp,   g_q);
    cudaGetSymbolAddress((void**)&kp,   g_k);
    cudaGetSymbolAddress((void**)&vp,   g_v);
    cudaGetSymbolAddress((void**)&attp, g_att);

    // 1) qkv projection (bf16x3 tensor cores) with scatter into (B,H,N,D)
    {
        dim3 grid(3 * CC / 128, M_ROWS / 128);
        mma_gemm<1><<<grid, 256>>>(x, W_qkv, b_qkv, nullptr, qp, kp, vp,
                                   M_ROWS, 3 * CC, CC);
    }

    // 2) tensor-core attention
    {
        const int smem_bytes = 6 * ATT_ELEMS * (int)sizeof(__nv_bfloat16);  // 179712
        cudaFuncSetAttribute(attn_mma_kernel, cudaFuncAttributeMaxDynamicSharedMemorySize,
                             smem_bytes);
        attn_mma_kernel<<<Bv * HH, 256, smem_bytes>>>(qp, kp, vp, attp);
    }

    // 3) depthwise conv + residual add into g_att rows 1:
    {
        const int total = Bv * GRID * GRID * CC;
        dwconv_kernel<<<total / 256, 256>>>(vp, dwc_w, dwc_b, attp);
    }

    // 4) output projection (bf16x3 tensor cores)
    {
        dim3 grid(CC / 128, M_ROWS / 128);
        mma_gemm<0><<<grid, 256>>>(attp, W_proj, b_proj, out,
                                   nullptr, nullptr, nullptr,
                                   M_ROWS, CC, CC);
    }
}

// round 6
// speedup vs baseline: 2.8888x; 1.2749x over previous
#include <cuda_runtime.h>
#include <cuda_bf16.h>
#include <math.h>

#define Bv 256
#define NT 197
#define CC 768
#define HH 12
#define DH 64
#define GRID 14
#define M_ROWS (Bv * NT)          // 50432 = 394*128

// ---------------- scratch ----------------
__device__ float g_q[(size_t)Bv * HH * NT * DH];
__device__ float g_k[(size_t)Bv * HH * NT * DH];
__device__ float g_v[(size_t)Bv * HH * NT * DH];
__device__ float g_att[(size_t)Bv * NT * CC];
__device__ __nv_bfloat16 g_xh[(size_t)M_ROWS * CC];
__device__ __nv_bfloat16 g_xl[(size_t)M_ROWS * CC];
__device__ __nv_bfloat16 g_ah[(size_t)M_ROWS * CC];
__device__ __nv_bfloat16 g_al[(size_t)M_ROWS * CC];
__device__ __nv_bfloat16 g_wqh[(size_t)CC * 3 * CC];
__device__ __nv_bfloat16 g_wql[(size_t)CC * 3 * CC];
__device__ __nv_bfloat16 g_wph[(size_t)CC * CC];
__device__ __nv_bfloat16 g_wpl[(size_t)CC * CC];

// ---------------- helpers ----------------
__device__ __forceinline__ unsigned smem_u32(const void* p) {
    return (unsigned)__cvta_generic_to_shared(p);
}
__device__ __forceinline__ void cp_async16(void* smem, const void* gmem) {
    unsigned s = smem_u32(smem);
    asm volatile("cp.async.cg.shared.global [%0], [%1], 16;\n" :: "r"(s), "l"(gmem));
}
__device__ __forceinline__ void ldsm_x4(unsigned& r0, unsigned& r1, unsigned& r2, unsigned& r3,
                                        unsigned addr) {
    asm volatile("ldmatrix.sync.aligned.m8n8.x4.shared.b16 {%0,%1,%2,%3}, [%4];\n"
                 : "=r"(r0), "=r"(r1), "=r"(r2), "=r"(r3) : "r"(addr));
}
__device__ __forceinline__ void ldsm_x4t(unsigned& r0, unsigned& r1, unsigned& r2, unsigned& r3,
                                         unsigned addr) {
    asm volatile("ldmatrix.sync.aligned.m8n8.x4.trans.shared.b16 {%0,%1,%2,%3}, [%4];\n"
                 : "=r"(r0), "=r"(r1), "=r"(r2), "=r"(r3) : "r"(addr));
}
__device__ __forceinline__ void ldsm_x2t(unsigned& r0, unsigned& r1, unsigned addr) {
    asm volatile("ldmatrix.sync.aligned.m8n8.x2.trans.shared.b16 {%0,%1}, [%2];\n"
                 : "=r"(r0), "=r"(r1) : "r"(addr));
}
__device__ __forceinline__ void mma16816(float* c, unsigned a0, unsigned a1, unsigned a2,
                                         unsigned a3, unsigned b0, unsigned b1) {
    asm volatile("mma.sync.aligned.m16n8k16.row.col.f32.bf16.bf16.f32 "
                 "{%0,%1,%2,%3}, {%4,%5,%6,%7}, {%8,%9}, {%0,%1,%2,%3};\n"
                 : "+f"(c[0]), "+f"(c[1]), "+f"(c[2]), "+f"(c[3])
                 : "r"(a0), "r"(a1), "r"(a2), "r"(a3), "r"(b0), "r"(b1));
}
__device__ __forceinline__ void split_store4(__nv_bfloat16* hp, __nv_bfloat16* lp, float4 v) {
    __nv_bfloat162 h0, h1, l0, l1;
    h0.x = __float2bfloat16_rn(v.x); l0.x = __float2bfloat16_rn(v.x - __bfloat162float(h0.x));
    h0.y = __float2bfloat16_rn(v.y); l0.y = __float2bfloat16_rn(v.y - __bfloat162float(h0.y));
    h1.x = __float2bfloat16_rn(v.z); l1.x = __float2bfloat16_rn(v.z - __bfloat162float(h1.x));
    h1.y = __float2bfloat16_rn(v.w); l1.y = __float2bfloat16_rn(v.w - __bfloat162float(h1.y));
    reinterpret_cast<__nv_bfloat162*>(hp)[0] = h0;
    reinterpret_cast<__nv_bfloat162*>(hp)[1] = h1;
    reinterpret_cast<__nv_bfloat162*>(lp)[0] = l0;
    reinterpret_cast<__nv_bfloat162*>(lp)[1] = l1;
}
__device__ __forceinline__ unsigned pack_hi(float x, float y) {
    __nv_bfloat162 t;
    t.x = __float2bfloat16_rn(x);
    t.y = __float2bfloat16_rn(y);
    return *reinterpret_cast<unsigned*>(&t);
}
__device__ __forceinline__ unsigned pack_lo(float x, float y) {
    __nv_bfloat162 t;
    __nv_bfloat16 hx = __float2bfloat16_rn(x);
    __nv_bfloat16 hy = __float2bfloat16_rn(y);
    t.x = __float2bfloat16_rn(x - __bfloat162float(hx));
    t.y = __float2bfloat16_rn(y - __bfloat162float(hy));
    return *reinterpret_cast<unsigned*>(&t);
}

// ---------------- fp32 -> bf16 hi/lo split (elementwise) ----------------
__global__ __launch_bounds__(256)
void cvt_split_kernel(const float* __restrict__ src, __nv_bfloat16* __restrict__ hi,
                      __nv_bfloat16* __restrict__ lo)
{
    const int i = blockIdx.x * 256 + threadIdx.x;
    float4 v = reinterpret_cast<const float4*>(src)[i];
    split_store4(hi + (size_t)i * 4, lo + (size_t)i * 4, v);
}

// ---------------- bf16x3 GEMM, cp.async double-buffered: 128x128x32, 256 thr ----------------
#define LDA 40    // 32 + 8 pad (bf16)
#define LDB 136   // 128 + 8 pad

template<int MODE>
__global__ __launch_bounds__(256, 2)
void mma_gemm_bf(const __nv_bfloat16* __restrict__ Agh, const __nv_bfloat16* __restrict__ Agl,
                 const __nv_bfloat16* __restrict__ Bgh, const __nv_bfloat16* __restrict__ Bgl,
                 const float* __restrict__ bias, float* __restrict__ C,
                 float* __restrict__ Cq, float* __restrict__ Ck, float* __restrict__ Cv,
                 int M, int N, int K)
{
    __shared__ alignas(16) __nv_bfloat16 sA[2][2][128][LDA];
    __shared__ alignas(16) __nv_bfloat16 sB[2][2][32][LDB];

    const int tid  = threadIdx.x;
    const int brow = blockIdx.y;
    const int bcol = blockIdx.x;
    const int lane = tid & 31;
    const int wid  = tid >> 5;
    const int wm = (wid & 1) * 64;
    const int wn = (wid >> 1) * 32;
    const int aRowBase = brow * 128;
    const int bColBase = bcol * 128;

    float acc[4][4][4];
    #pragma unroll
    for (int mt = 0; mt < 4; mt++)
        #pragma unroll
        for (int nt = 0; nt < 4; nt++)
            #pragma unroll
            for (int e = 0; e < 4; e++) acc[mt][nt][e] = 0.f;

    const int aRowLane = lane & 15;
    const int aColLane = (lane >> 4) << 3;
    const int bRowLane = lane & 15;

    // async stage loader: 8x 16B per thread
    auto issue = [&](int k0, int st) {
        #pragma unroll
        for (int c = 0; c < 2; c++) {
            const int chunk = tid + c * 256;          // 0..511
            const int arow = chunk >> 2;
            const int acol = (chunk & 3) << 3;
            const size_t aoff = (size_t)(aRowBase + arow) * K + k0 + acol;
            cp_async16(&sA[st][0][arow][acol], Agh + aoff);
            cp_async16(&sA[st][1][arow][acol], Agl + aoff);
            const int brw = chunk >> 4;
            const int bcl = (chunk & 15) << 3;
            const size_t boff = (size_t)(k0 + brw) * N + bColBase + bcl;
            cp_async16(&sB[st][0][brw][bcl], Bgh + boff);
            cp_async16(&sB[st][1][brw][bcl], Bgl + boff);
        }
    };

    const int NIT = K >> 5;
    issue(0, 0);
    asm volatile("cp.async.commit_group;\n");

    for (int it = 0; it < NIT; ++it) {
        if (it + 1 < NIT) {
            issue((it + 1) << 5, (it + 1) & 1);
            asm volatile("cp.async.commit_group;\n");
            asm volatile("cp.async.wait_group 1;\n");
        } else {
            asm volatile("cp.async.wait_group 0;\n");
        }
        __syncthreads();

        const int st = it & 1;
        const unsigned aBaseH = smem_u32(&sA[st][0][0][0]);
        const unsigned aBaseL = smem_u32(&sA[st][1][0][0]);
        const unsigned bBaseH = smem_u32(&sB[st][0][0][0]);
        const unsigned bBaseL = smem_u32(&sB[st][1][0][0]);

        #pragma unroll
        for (int ks = 0; ks < 2; ks++) {
            unsigned bhf[4][2], blf[4][2];
            #pragma unroll
            for (int nt = 0; nt < 4; nt++) {
                const unsigned boff = ((ks * 16 + bRowLane) * LDB + wn + nt * 8) * 2;
                ldsm_x2t(bhf[nt][0], bhf[nt][1], bBaseH + boff);
                ldsm_x2t(blf[nt][0], blf[nt][1], bBaseL + boff);
            }
            #pragma unroll
            for (int mt = 0; mt < 4; mt++) {
                const unsigned aoff = ((wm + mt * 16 + aRowLane) * LDA + ks * 16 + aColLane) * 2;
                unsigned ah0, ah1, ah2, ah3, al0, al1, al2, al3;
                ldsm_x4(ah0, ah1, ah2, ah3, aBaseH + aoff);
                ldsm_x4(al0, al1, al2, al3, aBaseL + aoff);
                #pragma unroll
                for (int nt = 0; nt < 4; nt++) {
                    mma16816(acc[mt][nt], ah0, ah1, ah2, ah3, bhf[nt][0], bhf[nt][1]);
                    mma16816(acc[mt][nt], al0, al1, al2, al3, bhf[nt][0], bhf[nt][1]);
                    mma16816(acc[mt][nt], ah0, ah1, ah2, ah3, blf[nt][0], blf[nt][1]);
                }
            }
        }
        __syncthreads();
    }

    const int trow = lane >> 2;
    const int tcol = (lane & 3) << 1;
    #pragma unroll
    for (int mt = 0; mt < 4; mt++) {
        #pragma unroll
        for (int nt = 0; nt < 4; nt++) {
            const int gc = bColBase + wn + nt * 8 + tcol;
            const float bia0 = bias[gc];
            const float bia1 = bias[gc + 1];
            #pragma unroll
            for (int half = 0; half < 2; half++) {
                const int gr = aRowBase + wm + mt * 16 + trow + half * 8;
                float2 val;
                val.x = acc[mt][nt][half * 2 + 0] + bia0;
                val.y = acc[mt][nt][half * 2 + 1] + bia1;
                if (MODE == 0) {
                    *(float2*)&C[(size_t)gr * N + gc] = val;
                } else {
                    const int b_ = gr / NT;
                    const int t  = gr - b_ * NT;
                    const int s  = gc / CC;
                    const int r  = gc - s * CC;
                    const int hh = r >> 6;
                    const int d  = r & 63;
                    const size_t idx = ((size_t)((b_ * HH + hh) * NT + t)) * DH + d;
                    float* dst = (s == 0) ? Cq : (s == 1) ? Ck : Cv;
                    *(float2*)&dst[idx] = val;
                }
            }
        }
    }
}

// ---------------- tensor-core attention: one CTA per (b,h), 416 threads (13 warps) ----------------
#define ATT_ROWS 208
#define ATT_LD 72
#define ATT_ELEMS (ATT_ROWS * ATT_LD)   // 14976

__global__ __launch_bounds__(416, 1)
void attn_mma_kernel(const float* __restrict__ q, const float* __restrict__ k,
                     const float* __restrict__ v, float* __restrict__ out)
{
    extern __shared__ __nv_bfloat16 sm[];
    __nv_bfloat16* smQH = sm;
    __nv_bfloat16* smQL = sm + ATT_ELEMS;
    __nv_bfloat16* smKH = sm + 2 * ATT_ELEMS;
    __nv_bfloat16* smKL = sm + 3 * ATT_ELEMS;
    __nv_bfloat16* smVH = sm + 4 * ATT_ELEMS;
    __nv_bfloat16* smVL = sm + 5 * ATT_ELEMS;

    const int bh = blockIdx.x;
    const int b  = bh / HH;
    const int h  = bh - b * HH;
    const size_t base = (size_t)bh * NT * DH;
    const int tid  = threadIdx.x;
    const int lane = tid & 31;
    const int wid  = tid >> 5;     // 0..12

    for (int s5 = tid; s5 < ATT_ROWS * 16; s5 += 416) {
        const int row = s5 >> 4;
        const int c4  = (s5 & 15) << 2;
        float4 qv, kv, vv;
        if (row < NT) {
            qv = *(const float4*)(q + base + (size_t)row * DH + c4);
            kv = *(const float4*)(k + base + (size_t)row * DH + c4);
            vv = *(const float4*)(v + base + (size_t)row * DH + c4);
            qv.x *= 0.125f; qv.y *= 0.125f; qv.z *= 0.125f; qv.w *= 0.125f;
        } else {
            qv = make_float4(0.f, 0.f, 0.f, 0.f);
            kv = qv; vv = qv;
        }
        const int off = row * ATT_LD + c4;
        split_store4(&smQH[off], &smQL[off], qv);
        split_store4(&smKH[off], &smKL[off], kv);
        split_store4(&smVH[off], &smVL[off], vv);
    }
    __syncthreads();

    const unsigned uQH = smem_u32(smQH);
    const unsigned uQL = smem_u32(smQL);
    const unsigned uKH = smem_u32(smKH);
    const unsigned uKL = smem_u32(smKL);
    const unsigned uVH = smem_u32(smVH);
    const unsigned uVL = smem_u32(smVL);

    // exactly 13 warps, 1 m-tile each
    const int m0 = wid * 16;

    unsigned qh[4][4], ql[4][4];
    {
        const int r  = m0 + (lane & 15);
        const int cb = (lane >> 4) << 3;
        #pragma unroll
        for (int ks = 0; ks < 4; ks++) {
            const unsigned off = (unsigned)((r * ATT_LD + ks * 16 + cb) * 2);
            ldsm_x4(qh[ks][0], qh[ks][1], qh[ks][2], qh[ks][3], uQH + off);
            ldsm_x4(ql[ks][0], ql[ks][1], ql[ks][2], ql[ks][3], uQL + off);
        }
    }

    // ---- S = Q K^T (25 n-tiles over 200 cols), fully unrolled ----
    float s[25][4];
    #pragma unroll
    for (int nt = 0; nt < 25; nt++)
        #pragma unroll
        for (int e = 0; e < 4; e++) s[nt][e] = 0.f;

    const int krow = lane & 7;
    const int kcol = ((lane >> 3) & 3) << 3;
    #pragma unroll
    for (int nt = 0; nt < 25; nt++) {
        const int n0 = nt * 8;
        unsigned kh[4][2], kl[4][2];
        {
            const unsigned o1 = (unsigned)(((n0 + krow) * ATT_LD + kcol) * 2);
            unsigned r0, r1, r2, r3;
            ldsm_x4(r0, r1, r2, r3, uKH + o1);
            kh[0][0] = r0; kh[0][1] = r1; kh[1][0] = r2; kh[1][1] = r3;
            ldsm_x4(r0, r1, r2, r3, uKH + o1 + 64);
            kh[2][0] = r0; kh[2][1] = r1; kh[3][0] = r2; kh[3][1] = r3;
            ldsm_x4(r0, r1, r2, r3, uKL + o1);
            kl[0][0] = r0; kl[0][1] = r1; kl[1][0] = r2; kl[1][1] = r3;
            ldsm_x4(r0, r1, r2, r3, uKL + o1 + 64);
            kl[2][0] = r0; kl[2][1] = r1; kl[3][0] = r2; kl[3][1] = r3;
        }
        #pragma unroll
        for (int ks = 0; ks < 4; ks++) {
            mma16816(s[nt], qh[ks][0], qh[ks][1], qh[ks][2], qh[ks][3], kh[ks][0], kh[ks][1]);
            mma16816(s[nt], ql[ks][0], ql[ks][1], ql[ks][2], ql[ks][3], kh[ks][0], kh[ks][1]);
            mma16816(s[nt], qh[ks][0], qh[ks][1], qh[ks][2], qh[ks][3], kl[ks][0], kl[ks][1]);
        }
    }

    // ---- softmax ----
    {
        const int col0 = 192 + ((lane & 3) << 1);
        if (col0     >= NT) { s[24][0] = -1e30f; s[24][2] = -1e30f; }
        if (col0 + 1 >= NT) { s[24][1] = -1e30f; s[24][3] = -1e30f; }
    }
    float mx0 = -1e30f, mx1 = -1e30f;
    #pragma unroll
    for (int nt = 0; nt < 25; nt++) {
        mx0 = fmaxf(mx0, fmaxf(s[nt][0], s[nt][1]));
        mx1 = fmaxf(mx1, fmaxf(s[nt][2], s[nt][3]));
    }
    mx0 = fmaxf(mx0, __shfl_xor_sync(0xffffffffu, mx0, 1));
    mx0 = fmaxf(mx0, __shfl_xor_sync(0xffffffffu, mx0, 2));
    mx1 = fmaxf(mx1, __shfl_xor_sync(0xffffffffu, mx1, 1));
    mx1 = fmaxf(mx1, __shfl_xor_sync(0xffffffffu, mx1, 2));

    float sum0 = 0.f, sum1 = 0.f;
    #pragma unroll
    for (int nt = 0; nt < 25; nt++) {
        const float e0 = __expf(s[nt][0] - mx0);
        const float e1 = __expf(s[nt][1] - mx0);
        const float e2 = __expf(s[nt][2] - mx1);
        const float e3 = __expf(s[nt][3] - mx1);
        s[nt][0] = e0; s[nt][1] = e1; s[nt][2] = e2; s[nt][3] = e3;
        sum0 += e0 + e1; sum1 += e2 + e3;
    }
    sum0 += __shfl_xor_sync(0xffffffffu, sum0, 1);
    sum0 += __shfl_xor_sync(0xffffffffu, sum0, 2);
    sum1 += __shfl_xor_sync(0xffffffffu, sum1, 1);
    sum1 += __shfl_xor_sync(0xffffffffu, sum1, 2);
    const float inv0 = 1.0f / sum0;
    const float inv1 = 1.0f / sum1;

    // ---- O = P V, pack P in-loop, fully unrolled ----
    float o[8][4];
    #pragma unroll
    for (int nt = 0; nt < 8; nt++)
        #pragma unroll
        for (int e = 0; e < 4; e++) o[nt][e] = 0.f;

    const int vrow = ((lane >> 3) & 1) * 8 + (lane & 7);
    const int vcol = (lane >> 4) << 3;
    #pragma unroll
    for (int ks = 0; ks < 13; ks++) {
        unsigned ah0, ah1, ah2, ah3, al0, al1, al2, al3;
        if (ks < 12) {
            ah0 = pack_hi(s[2*ks][0],   s[2*ks][1]);   ah1 = pack_hi(s[2*ks][2],   s[2*ks][3]);
            ah2 = pack_hi(s[2*ks+1][0], s[2*ks+1][1]); ah3 = pack_hi(s[2*ks+1][2], s[2*ks+1][3]);
            al0 = pack_lo(s[2*ks][0],   s[2*ks][1]);   al1 = pack_lo(s[2*ks][2],   s[2*ks][3]);
            al2 = pack_lo(s[2*ks+1][0], s[2*ks+1][1]); al3 = pack_lo(s[2*ks+1][2], s[2*ks+1][3]);
        } else {
            ah0 = pack_hi(s[24][0], s[24][1]); ah1 = pack_hi(s[24][2], s[24][3]);
            al0 = pack_lo(s[24][0], s[24][1]); al1 = pack_lo(s[24][2], s[24][3]);
            ah2 = 0u; ah3 = 0u; al2 = 0u; al3 = 0u;
        }
        const int k0 = ks * 16;
        #pragma unroll
        for (int np = 0; np < 4; np++) {
            const unsigned off = (unsigned)(((k0 + vrow) * ATT_LD + np * 16 + vcol) * 2);
            unsigned vh0, vh1, vh2, vh3, vl0, vl1, vl2, vl3;
            ldsm_x4t(vh0, vh1, vh2, vh3, uVH + off);
            ldsm_x4t(vl0, vl1, vl2, vl3, uVL + off);
            mma16816(o[2 * np],     ah0, ah1, ah2, ah3, vh0, vh1);
            mma16816(o[2 * np],     al0, al1, al2, al3, vh0, vh1);
            mma16816(o[2 * np],     ah0, ah1, ah2, ah3, vl0, vl1);
            mma16816(o[2 * np + 1], ah0, ah1, ah2, ah3, vh2, vh3);
            mma16816(o[2 * np + 1], al0, al1, al2, al3, vh2, vh3);
            mma16816(o[2 * np + 1], ah0, ah1, ah2, ah3, vl2, vl3);
        }
    }

    // ---- store ----
    const int r0 = m0 + (lane >> 2);
    const int r1 = r0 + 8;
    const int cb = h * DH + ((lane & 3) << 1);
    if (r0 < NT) {
        float* op = out + ((size_t)b * NT + r0) * CC + cb;
        #pragma unroll
        for (int nt = 0; nt < 8; nt++) {
            float2 val; val.x = o[nt][0] * inv0; val.y = o[nt][1] * inv0;
            *(float2*)(op + nt * 8) = val;
        }
    }
    if (r1 < NT) {
        float* op = out + ((size_t)b * NT + r1) * CC + cb;
        #pragma unroll
        for (int nt = 0; nt < 8; nt++) {
            float2 val; val.x = o[nt][2] * inv1; val.y = o[nt][3] * inv1;
            *(float2*)(op + nt * 8) = val;
        }
    }
}

// ---------------- depthwise 3x3 conv on V (tokens 1:), residual add ----------------
__global__ __launch_bounds__(256)
void dwconv_kernel(const float* __restrict__ v, const float* __restrict__ wgt,
                   const float* __restrict__ bias, float* __restrict__ out)
{
    const int idx = blockIdx.x * 256 + threadIdx.x;
    const int c  = idx % CC;
    const int sp = (idx / CC) % (GRID * GRID);
    const int b  = idx / (CC * GRID * GRID);
    const int y = sp / GRID, x = sp - y * GRID;
    const int hh = c >> 6, d = c & 63;

    const float* vb = v + ((size_t)(b * HH + hh) * NT) * DH + d;
    float s = bias[c];
    #pragma unroll
    for (int ky = 0; ky < 3; ky++) {
        const int yy = y + ky - 1;
        if (yy < 0 || yy >= GRID) continue;
        #pragma unroll
        for (int kx = 0; kx < 3; kx++) {
            const int xx = x + kx - 1;
            if (xx < 0 || xx >= GRID) continue;
            const int t = 1 + yy * GRID + xx;
            s = fmaf(vb[(size_t)t * DH], wgt[c * 9 + ky * 3 + kx], s);
        }
    }
    out[((size_t)b * NT + 1 + sp) * CC + c] += s;
}

// ---------------- launch ----------------
extern "C" void kernel_launch(void* const* d_in, const int* in_sizes, int n_in,
                              void* d_out, int out_size)
{
    const float* x      = (const float*)d_in[0];
    const float* W_qkv  = (const float*)d_in[1];
    const float* b_qkv  = (const float*)d_in[2];
    const float* W_proj = (const float*)d_in[3];
    const float* b_proj = (const float*)d_in[4];
    const float* dwc_w  = (const float*)d_in[5];
    const float* dwc_b  = (const float*)d_in[6];
    float* out = (float*)d_out;

    float *qp, *kp, *vp, *attp;
    __nv_bfloat16 *xh, *xl, *ah, *al, *wqh, *wql, *wph, *wpl;
    cudaGetSymbolAddress((void**)&qp,   g_q);
    cudaGetSymbolAddress((void**)&kp,   g_k);
    cudaGetSymbolAddress((void**)&vp,   g_v);
    cudaGetSymbolAddress((void**)&attp, g_att);
    cudaGetSymbolAddress((void**)&xh,  g_xh);
    cudaGetSymbolAddress((void**)&xl,  g_xl);
    cudaGetSymbolAddress((void**)&ah,  g_ah);
    cudaGetSymbolAddress((void**)&al,  g_al);
    cudaGetSymbolAddress((void**)&wqh, g_wqh);
    cudaGetSymbolAddress((void**)&wql, g_wql);
    cudaGetSymbolAddress((void**)&wph, g_wph);
    cudaGetSymbolAddress((void**)&wpl, g_wpl);

    // 0) split-convert x, W_qkv, W_proj
    cvt_split_kernel<<<(M_ROWS * CC / 4) / 256, 256>>>(x, xh, xl);
    cvt_split_kernel<<<(CC * 3 * CC / 4) / 256, 256>>>(W_qkv, wqh, wql);
    cvt_split_kernel<<<(CC * CC / 4) / 256, 256>>>(W_proj, wph, wpl);

    // 1) qkv projection with scatter into (B,H,N,D)
    {
        dim3 grid(3 * CC / 128, M_ROWS / 128);
        mma_gemm_bf<1><<<grid, 256>>>(xh, xl, wqh, wql, b_qkv, nullptr, qp, kp, vp,
                                      M_ROWS, 3 * CC, CC);
    }

    // 2) tensor-core attention
    {
        const int smem_bytes = 6 * ATT_ELEMS * (int)sizeof(__nv_bfloat16);  // 179712
        cudaFuncSetAttribute(attn_mma_kernel, cudaFuncAttributeMaxDynamicSharedMemorySize,
                             smem_bytes);
        attn_mma_kernel<<<Bv * HH, 416, smem_bytes>>>(qp, kp, vp, attp);
    }

    // 3) depthwise conv + residual add into g_att rows 1:
    {
        const int total = Bv * GRID * GRID * CC;
        dwconv_kernel<<<total / 256, 256>>>(vp, dwc_w, dwc_b, attp);
    }

    // 4) split-convert att, then output projection
    cvt_split_kernel<<<(M_ROWS * CC / 4) / 256, 256>>>(attp, ah, al);
    {
        dim3 grid(CC / 128, M_ROWS / 128);
        mma_gemm_bf<0><<<grid, 256>>>(ah, al, wph, wpl, b_proj, out,
                                      nullptr, nullptr, nullptr,
                                      M_ROWS, CC, CC);
    }
}